// round 4
// baseline (speedup 1.0000x reference)
#include <cuda_runtime.h>
#include <math.h>

#define B_ 2
#define N_ 2048
#define F_ 256
#define NEGC (-1e15f)

// ---------------- scratch (no allocations allowed) ----------------
__device__ float g_bufA[B_*N_*F_];
__device__ float g_bufB[B_*N_*F_];
__device__ float g_Wh  [B_*N_*F_];
__device__ float g_Wcat[F_*F_];
__device__ float g_s1  [B_*8*N_];
__device__ float g_s2  [B_*8*N_];
__device__ float g_mx  [B_*8*N_];   // per-row max of s2 over unmasked j

__device__ __forceinline__ float eluf(float x){ return x > 0.f ? x : expm1f(x); }

// packed f32x2 helpers (FFMA2 path: only reachable via PTX fma.rn.f32x2)
#define FMA2(acc, p, w) asm("fma.rn.f32x2 %0, %1, %2, %0;" : "+l"(acc) : "l"(p), "l"(w))
__device__ __forceinline__ unsigned long long bcast2(float x){
  unsigned long long r; unsigned xi = __float_as_uint(x);
  asm("mov.b64 %0, {%1, %1};" : "=l"(r) : "r"(xi));
  return r;
}
__device__ __forceinline__ float2 unpack2(unsigned long long v){
  unsigned lo, hi;
  asm("mov.b64 {%0, %1}, %2;" : "=r"(lo), "=r"(hi) : "l"(v));
  return make_float2(__uint_as_float(lo), __uint_as_float(hi));
}

// pack W_heads[l] (H=8, F, O=32) -> g_Wcat[F][F] with Wcat[f][h*32+o] = W[h][f][o]
__global__ void pack_w_kernel(const float* __restrict__ Wsrc){
  int idx = blockIdx.x*256 + threadIdx.x;   // 0..65535
  int col = idx & 255, f = idx >> 8;
  int h = col >> 5, o = col & 31;
  g_Wcat[idx] = Wsrc[(h*F_ + f)*32 + o];
}

// C[M,256] = A[M,256] @ W[256,256] ; M = B_*N_ = 4096 ; C = g_Wh
__global__ __launch_bounds__(256) void gemm_kernel(const float* __restrict__ Aext, int asel,
                                                   const float* __restrict__ Wext, int wsel){
  const float* A = (asel==0) ? Aext : (asel==1 ? g_bufA : g_bufB);
  const float* W = (wsel==0) ? Wext : g_Wcat;
  float* C = g_Wh;
  __shared__ float As[16][68];
  __shared__ float Bs[16][68];
  int bm = blockIdx.y*64, bn = blockIdx.x*64;
  int tid = threadIdx.x;
  int tm = (tid>>4)<<2, tn = (tid&15)<<2;
  float acc[4][4];
  #pragma unroll
  for(int i=0;i<4;i++){
    #pragma unroll
    for(int j=0;j<4;j++) acc[i][j]=0.f;
  }
  for(int k0=0;k0<256;k0+=16){
    __syncthreads();
    #pragma unroll
    for(int t=0;t<4;t++){
      int u = tid + t*256;               // 0..1023
      int r = u>>4, c = u&15;
      As[c][r]   = A[(bm+r)*256 + k0 + c];
      int r2 = u>>6, c2 = u&63;
      Bs[r2][c2] = W[(k0+r2)*256 + bn + c2];
    }
    __syncthreads();
    #pragma unroll
    for(int kk=0;kk<16;kk++){
      float4 a4 = *(const float4*)&As[kk][tm];
      float4 b4 = *(const float4*)&Bs[kk][tn];
      float av[4] = {a4.x,a4.y,a4.z,a4.w};
      float bv[4] = {b4.x,b4.y,b4.z,b4.w};
      #pragma unroll
      for(int i=0;i<4;i++){
        #pragma unroll
        for(int j=0;j<4;j++) acc[i][j] += av[i]*bv[j];
      }
    }
  }
  #pragma unroll
  for(int i=0;i<4;i++){
    float4 v = make_float4(acc[i][0],acc[i][1],acc[i][2],acc[i][3]);
    *(float4*)&C[(bm+tm+i)*256 + bn + tn] = v;
  }
}

// s1[b,h,n] = Wh[b,n,h*O:..]·a1h ; s2 likewise. One warp per row; rows = B*H*N.
__global__ void scores_kernel(const float* __restrict__ avec, int H, int O){
  int lane = threadIdx.x & 31;
  int wid  = threadIdx.x >> 5;
  int row  = blockIdx.x*8 + wid;          // grid sized exactly
  int n = row % N_;
  int h = (row / N_) % H;
  int b = row / (N_*H);
  const float* w = g_Wh + (b*N_ + n)*F_ + h*O;
  const float* a = avec + h*2*O;
  float r1=0.f, r2=0.f;
  for(int o=lane;o<O;o+=32){
    float v = w[o];
    r1 += v*a[o];
    r2 += v*a[O+o];
  }
  #pragma unroll
  for(int d=16;d;d>>=1){
    r1 += __shfl_xor_sync(0xffffffffu, r1, d);
    r2 += __shfl_xor_sync(0xffffffffu, r2, d);
  }
  if(lane==0){ g_s1[row]=r1; g_s2[row]=r2; }
}

// Exact softmax row max: lrelu is monotone in s2, so max_j e(i,j) over the
// unmasked set = lrelu(s1_i + max_{j in nbr(i)} s2_j). Compute max s2 per
// (b,i) row for all H heads in one adjacency sweep. One warp per row.
__global__ __launch_bounds__(256) void rowmax_kernel(const int* __restrict__ adj, int H){
  int lane = threadIdx.x & 31;
  int row  = blockIdx.x*8 + (threadIdx.x>>5);   // b*N + i, grid = B*N/8
  int b = row >> 11;
  int i = row & (N_-1);
  const int* ar = adj + row*N_;
  const float* s2b = g_s2 + b*H*N_;
  float mx[8];
  #pragma unroll
  for(int k=0;k<8;k++) mx[k] = -INFINITY;
  for(int j=lane;j<N_;j+=32){
    if(ar[j]){
      for(int hh=0;hh<H;hh++) mx[hh] = fmaxf(mx[hh], s2b[hh*N_ + j]);
    }
  }
  for(int hh=0;hh<H;hh++){
    float v = mx[hh];
    #pragma unroll
    for(int d=16;d;d>>=1) v = fmaxf(v, __shfl_xor_sync(0xffffffffu, v, d));
    if(lane==0) g_mx[(b*H+hh)*N_ + i] = v;
  }
}

// Fused masked-softmax attention + elu, single pass (row max precomputed).
// CTA = (b, 32-query block), all 256 out cols.
// 256 thr = 16 col-groups(16 cols) x 16 query slots; 2 queries per thread.
// P-dot-V accumulation uses packed fma.rn.f32x2 (FFMA2).
__global__ __launch_bounds__(256) void attn_kernel(const int* __restrict__ adj,
        float* __restrict__ out_ext, int osel, int H, int O, int elu2){
  float* out = (osel==0) ? out_ext : (osel==1 ? g_bufA : g_bufB);
  const float* Wh = g_Wh;
  int bi = blockIdx.x;                 // 0..127
  int b  = bi >> 6;
  int i0 = (bi & 63) << 5;
  int tid = threadIdx.x;
  int g  = tid & 15, is = tid >> 4;
  int c0 = g << 4;
  int h  = c0 / O;                     // H=8 -> g>>1 ; H=1 -> 0
  int q0 = i0 + is, q1 = q0 + 16;

  // group-padded j-tile: 16 groups of 16 floats, stride 20 floats (80B, 16B-aligned)
  __shared__ __align__(16) float Whs[32*320];
  __shared__ float s2s[8][33];
  __shared__ unsigned mskbits[32];

  unsigned long long acc0p[8], acc1p[8];
  #pragma unroll
  for(int k=0;k<8;k++){ acc0p[k]=0ull; acc1p[k]=0ull; }
  float l0=0.f, l1=0.f;

  const float* s1p = g_s1 + (b*H + h)*N_;
  const float* mxp = g_mx + (b*H + h)*N_;
  float s1v0 = s1p[q0], s1v1 = s1p[q1];
  float mx0 = mxp[q0],  mx1 = mxp[q1];
  float u0 = s1v0 + mx0; u0 = u0>0.f ? u0 : 0.2f*u0;
  float u1 = s1v1 + mx1; u1 = u1>0.f ? u1 : 0.2f*u1;
  float m0 = (mx0 == -INFINITY) ? NEGC : u0;   // all-masked row -> uniform softmax
  float m1 = (mx1 == -INFINITY) ? NEGC : u1;
  const float* s2p = g_s2 + b*H*N_;
  int lane = tid & 31;

  for(int j0=0;j0<N_;j0+=32){
    __syncthreads();
    // load 32x256 Wh j-tile
    #pragma unroll
    for(int t=0;t<8;t++){
      int u = tid + t*256;               // 0..2047 float4 units
      int r = u>>6, c4 = u&63;
      int gg = c4>>2, k4 = c4&3;
      float4 v = *(const float4*)(Wh + ((b*N_ + j0 + r)<<8) + (c4<<2));
      *(float4*)(Whs + r*320 + gg*20 + (k4<<2)) = v;
    }
    // adjacency -> packed bitmasks (one warp per row, 4 rows/warp)
    #pragma unroll
    for(int t=0;t<4;t++){
      int r = (tid>>5) + t*8;
      int a = adj[(b*N_ + i0 + r)*N_ + j0 + lane];
      unsigned bal = __ballot_sync(0xffffffffu, a != 0);
      if(lane==0) mskbits[r] = bal;
    }
    if(tid < H*32){
      int hh = tid>>5, jj = tid&31;
      s2s[hh][jj] = s2p[hh*N_ + j0 + jj];
    }
    __syncthreads();

    unsigned mb0 = mskbits[is], mb1 = mskbits[is+16];

    // single pass: p = exp(e-m) (p<=1 guaranteed), packed FFMA2 accumulate
    #pragma unroll 4
    for(int jj=0;jj<32;jj++){
      float s2v = s2s[h][jj];
      float e0 = s1v0 + s2v; e0 = e0>0.f ? e0 : 0.2f*e0; e0 = ((mb0>>jj)&1u) ? e0 : NEGC;
      float e1 = s1v1 + s2v; e1 = e1>0.f ? e1 : 0.2f*e1; e1 = ((mb1>>jj)&1u) ? e1 : NEGC;
      float p0 = __expf(e0-m0); l0 += p0;
      float p1 = __expf(e1-m1); l1 += p1;
      unsigned long long P0 = bcast2(p0), P1 = bcast2(p1);
      const ulonglong2* wp = (const ulonglong2*)(Whs + jj*320 + g*20);
      ulonglong2 wa = wp[0], wb = wp[1], wc = wp[2], wd = wp[3];
      FMA2(acc0p[0],P0,wa.x); FMA2(acc0p[1],P0,wa.y);
      FMA2(acc0p[2],P0,wb.x); FMA2(acc0p[3],P0,wb.y);
      FMA2(acc0p[4],P0,wc.x); FMA2(acc0p[5],P0,wc.y);
      FMA2(acc0p[6],P0,wd.x); FMA2(acc0p[7],P0,wd.y);
      FMA2(acc1p[0],P1,wa.x); FMA2(acc1p[1],P1,wa.y);
      FMA2(acc1p[2],P1,wb.x); FMA2(acc1p[3],P1,wb.y);
      FMA2(acc1p[4],P1,wc.x); FMA2(acc1p[5],P1,wc.y);
      FMA2(acc1p[6],P1,wd.x); FMA2(acc1p[7],P1,wd.y);
    }
  }

  float inv0 = 1.f/l0, inv1 = 1.f/l1;
  float v0[16], v1[16];
  #pragma unroll
  for(int k=0;k<8;k++){
    float2 a = unpack2(acc0p[k]); v0[2*k] = a.x; v0[2*k+1] = a.y;
    float2 c = unpack2(acc1p[k]); v1[2*k] = c.x; v1[2*k+1] = c.y;
  }
  float* p0o = out + ((b*N_ + q0)<<8) + c0;
  float* p1o = out + ((b*N_ + q1)<<8) + c0;
  #pragma unroll
  for(int k4=0;k4<4;k4++){
    float4 o0, o1; float t;
    t = v0[k4*4+0]*inv0; t=eluf(t); if(elu2) t=eluf(t); o0.x=t;
    t = v0[k4*4+1]*inv0; t=eluf(t); if(elu2) t=eluf(t); o0.y=t;
    t = v0[k4*4+2]*inv0; t=eluf(t); if(elu2) t=eluf(t); o0.z=t;
    t = v0[k4*4+3]*inv0; t=eluf(t); if(elu2) t=eluf(t); o0.w=t;
    t = v1[k4*4+0]*inv1; t=eluf(t); if(elu2) t=eluf(t); o1.x=t;
    t = v1[k4*4+1]*inv1; t=eluf(t); if(elu2) t=eluf(t); o1.y=t;
    t = v1[k4*4+2]*inv1; t=eluf(t); if(elu2) t=eluf(t); o1.z=t;
    t = v1[k4*4+3]*inv1; t=eluf(t); if(elu2) t=eluf(t); o1.w=t;
    *(float4*)(p0o + (k4<<2)) = o0;
    *(float4*)(p1o + (k4<<2)) = o1;
  }
}

extern "C" void kernel_launch(void* const* d_in, const int* in_sizes, int n_in,
                              void* d_out, int out_size){
  const float* x       = (const float*)d_in[0];
  const int*   adj     = (const int*)  d_in[1];
  const float* W_heads = (const float*)d_in[2];  // [3,8,256,32]
  const float* a_heads = (const float*)d_in[3];  // [3,8,64]
  const float* W_out   = (const float*)d_in[4];  // [3,256,256]
  const float* a_out   = (const float*)d_in[5];  // [3,512]
  float* outp = (float*)d_out;

  for(int l=0;l<3;l++){
    // ---- multi-head pass ----
    pack_w_kernel<<<256,256>>>(W_heads + l*8*F_*32);
    gemm_kernel<<<dim3(4,64),256>>>(x, (l==0)?0:1, (const float*)nullptr, 1);
    scores_kernel<<<(B_*8*N_)/8,256>>>(a_heads + l*8*64, 8, 32);
    rowmax_kernel<<<(B_*N_)/8,256>>>(adj, 8);
    attn_kernel<<<128,256>>>(adj, (float*)nullptr, 2, 8, 32, 0);
    // ---- single-head output pass ----
    gemm_kernel<<<dim3(4,64),256>>>((const float*)nullptr, 2, W_out + l*F_*F_, 0);
    scores_kernel<<<(B_*N_)/8,256>>>(a_out + l*2*F_, 1, 256);
    rowmax_kernel<<<(B_*N_)/8,256>>>(adj, 1);
    attn_kernel<<<128,256>>>(adj, outp, (l==2)?0:1, 1, 256, 1);
  }
}

// round 5
// speedup vs baseline: 1.2076x; 1.2076x over previous
#include <cuda_runtime.h>
#include <math.h>

#define B_ 2
#define N_ 2048
#define F_ 256
#define NEGC (-1e15f)
#define LOG2E 1.4426950408889634f

// ---------------- scratch (no allocations allowed) ----------------
__device__ float    g_bufA[B_*N_*F_];
__device__ float    g_bufB[B_*N_*F_];
__device__ float    g_Wh  [B_*N_*F_];
__device__ float    g_Wcat[F_*F_];
__device__ float    g_s1  [B_*8*N_];
__device__ float    g_s2  [B_*8*N_];
__device__ float    g_mx2 [B_*8];          // global max of s2 per (b,h)
__device__ unsigned g_msk [B_*N_*(N_/32)]; // packed adjacency bits

__device__ __forceinline__ float eluf(float x){ return x > 0.f ? x : expm1f(x); }
__device__ __forceinline__ float ex2f(float x){ float r; asm("ex2.approx.f32 %0, %1;":"=f"(r):"f"(x)); return r; }

// packed f32x2 helpers (FFMA2 path: only reachable via PTX fma.rn.f32x2)
#define FMA2(acc, p, w) asm("fma.rn.f32x2 %0, %1, %2, %0;" : "+l"(acc) : "l"(p), "l"(w))
__device__ __forceinline__ unsigned long long bcast2(float x){
  unsigned long long r; unsigned xi = __float_as_uint(x);
  asm("mov.b64 %0, {%1, %1};" : "=l"(r) : "r"(xi));
  return r;
}
__device__ __forceinline__ float2 unpack2(unsigned long long v){
  unsigned lo, hi;
  asm("mov.b64 {%0, %1}, %2;" : "=r"(lo), "=r"(hi) : "l"(v));
  return make_float2(__uint_as_float(lo), __uint_as_float(hi));
}

// pack adjacency into bitmask words, once per launch. warp per row.
__global__ void maskpack_kernel(const int* __restrict__ adj){
  int row  = blockIdx.x*8 + (threadIdx.x>>5);   // 0..B*N-1, grid=512
  int lane = threadIdx.x & 31;
  const int* ar = adj + (long)row*N_;
  unsigned* mw = g_msk + row*(N_/32);
  for(int w=0; w<N_/32; w++){
    int a = ar[w*32 + lane];
    unsigned bal = __ballot_sync(0xffffffffu, a != 0);
    if(lane==0) mw[w] = bal;
  }
}

// pack W_heads[l] (H=8, F, O=32) -> g_Wcat[F][F] with Wcat[f][h*32+o] = W[h][f][o]
__global__ void pack_w_kernel(const float* __restrict__ Wsrc){
  int idx = blockIdx.x*256 + threadIdx.x;   // 0..65535
  int col = idx & 255, f = idx >> 8;
  int h = col >> 5, o = col & 31;
  g_Wcat[idx] = Wsrc[(h*F_ + f)*32 + o];
}

// C[M,256] = A[M,256] @ W[256,256] ; M = B_*N_ = 4096 ; C = g_Wh. FFMA2 inner.
__global__ __launch_bounds__(256) void gemm_kernel(const float* __restrict__ Aext, int asel,
                                                   const float* __restrict__ Wext, int wsel){
  const float* A = (asel==0) ? Aext : (asel==1 ? g_bufA : g_bufB);
  const float* W = (wsel==0) ? Wext : g_Wcat;
  float* C = g_Wh;
  __shared__ __align__(16) float As[16][68];
  __shared__ __align__(16) float Bs[16][68];
  int bm = blockIdx.y*64, bn = blockIdx.x*64;
  int tid = threadIdx.x;
  int tm = (tid>>4)<<2, tn = (tid&15)<<2;
  unsigned long long accp[4][2];
  #pragma unroll
  for(int i=0;i<4;i++){ accp[i][0]=0ull; accp[i][1]=0ull; }
  for(int k0=0;k0<256;k0+=16){
    __syncthreads();
    #pragma unroll
    for(int t=0;t<4;t++){
      int u = tid + t*256;               // 0..1023
      int r = u>>4, c = u&15;
      As[c][r]   = A[(bm+r)*256 + k0 + c];
      int r2 = u>>6, c2 = u&63;
      Bs[r2][c2] = W[(k0+r2)*256 + bn + c2];
    }
    __syncthreads();
    #pragma unroll
    for(int kk=0;kk<16;kk++){
      float4 a4 = *(const float4*)&As[kk][tm];
      ulonglong2 b2 = *(const ulonglong2*)&Bs[kk][tn];
      unsigned long long P;
      P = bcast2(a4.x); FMA2(accp[0][0],P,b2.x); FMA2(accp[0][1],P,b2.y);
      P = bcast2(a4.y); FMA2(accp[1][0],P,b2.x); FMA2(accp[1][1],P,b2.y);
      P = bcast2(a4.z); FMA2(accp[2][0],P,b2.x); FMA2(accp[2][1],P,b2.y);
      P = bcast2(a4.w); FMA2(accp[3][0],P,b2.x); FMA2(accp[3][1],P,b2.y);
    }
  }
  #pragma unroll
  for(int i=0;i<4;i++){
    float2 lo = unpack2(accp[i][0]), hi = unpack2(accp[i][1]);
    *(float4*)&C[(bm+tm+i)*256 + bn + tn] = make_float4(lo.x,lo.y,hi.x,hi.y);
  }
}

// s1[b,h,n] = Wh[b,n,h*O:..]·a1h ; s2 likewise. One warp per row; rows = B*H*N.
__global__ void scores_kernel(const float* __restrict__ avec, int H, int O){
  int lane = threadIdx.x & 31;
  int wid  = threadIdx.x >> 5;
  int row  = blockIdx.x*8 + wid;          // grid sized exactly
  int n = row % N_;
  int h = (row / N_) % H;
  int b = row / (N_*H);
  const float* w = g_Wh + (b*N_ + n)*F_ + h*O;
  const float* a = avec + h*2*O;
  float r1=0.f, r2=0.f;
  for(int o=lane;o<O;o+=32){
    float v = w[o];
    r1 += v*a[o];
    r2 += v*a[O+o];
  }
  #pragma unroll
  for(int d=16;d;d>>=1){
    r1 += __shfl_xor_sync(0xffffffffu, r1, d);
    r2 += __shfl_xor_sync(0xffffffffu, r2, d);
  }
  if(lane==0){ g_s1[row]=r1; g_s2[row]=r2; }
}

// Global (unmasked) max of s2 per (b,h): a valid softmax upper bound via
// lrelu monotonicity; avoids any adjacency sweep. grid = B*H.
__global__ void s2max_kernel(int H){
  int bh = blockIdx.x;
  const float* p = g_s2 + bh*N_;
  float v = -INFINITY;
  for(int j=threadIdx.x;j<N_;j+=256) v = fmaxf(v, p[j]);
  __shared__ float red[8];
  int lane = threadIdx.x & 31, wid = threadIdx.x >> 5;
  #pragma unroll
  for(int d=16;d;d>>=1) v = fmaxf(v, __shfl_xor_sync(0xffffffffu, v, d));
  if(lane==0) red[wid] = v;
  __syncthreads();
  if(wid==0){
    v = red[lane&7];
    #pragma unroll
    for(int d=4;d;d>>=1) v = fmaxf(v, __shfl_xor_sync(0xffffffffu, v, d));
    if(lane==0) g_mx2[bh] = v;
  }
}

// Fused masked-softmax attention + elu, single pass, FFMA2 P·V.
// CTA = (b, 32-query block) x all 256 cols. 256 thr: warp w covers
// col-groups (w&1)*8..+8 and query-slots (w>>1)*4..+4 -> per LDS.128 a warp
// touches 8 bank-distinct lines (stride-20 layout) with 4-lane broadcast:
// 1 wavefront/instr (was 2-phase conflicted with g=tid&15 mapping).
__global__ __launch_bounds__(256) void attn_kernel(float* __restrict__ out_ext,
        int osel, int H, int O, int elu2){
  float* out = (osel==0) ? out_ext : (osel==1 ? g_bufA : g_bufB);
  const float* Wh = g_Wh;
  int bi = blockIdx.x;                 // 0..127
  int b  = bi >> 6;
  int i0 = (bi & 63) << 5;
  int tid = threadIdx.x;
  int w  = tid >> 5, lane = tid & 31;
  int g  = (w&1)*8 + (lane>>2);        // 16 col groups of 16
  int is = (w>>1)*4 + (lane&3);        // 16 query slots
  int c0 = g << 4;
  int h  = c0 / O;                     // H=8 -> g>>1 ; H=1 -> 0
  int q0 = i0 + is, q1 = q0 + 16;

  __shared__ __align__(16) float Whs[32*320];  // 16 groups, stride 20 floats
  __shared__ float s2s[8][33];
  __shared__ unsigned mskbits[32];

  unsigned long long acc0p[8], acc1p[8];
  #pragma unroll
  for(int k=0;k<8;k++){ acc0p[k]=0ull; acc1p[k]=0ull; }
  float l0=0.f, l1=0.f;

  const float* s1p = g_s1 + (b*H + h)*N_;
  float s1v0 = s1p[q0], s1v1 = s1p[q1];
  float mxv  = g_mx2[b*H + h];
  float u0 = s1v0 + mxv; u0 = fmaxf(u0, 0.2f*u0);
  float u1 = s1v1 + mxv; u1 = fmaxf(u1, 0.2f*u1);
  float nm0 = -u0*LOG2E, nm1 = -u1*LOG2E;   // exp(e-m) = ex2(e*log2e + nm)
  const float* s2p = g_s2 + b*H*N_;
  const unsigned* mrow = g_msk + (b*N_ + i0)*(N_/32);

  for(int j0=0;j0<N_;j0+=32){
    __syncthreads();
    // load 32x256 Wh j-tile into group-padded layout
    #pragma unroll
    for(int t=0;t<8;t++){
      int u = tid + t*256;               // 0..2047 float4 units
      int r = u>>6, c4 = u&63;
      int gg = c4>>2, k4 = c4&3;
      float4 v = *(const float4*)(Wh + ((b*N_ + j0 + r)<<8) + (c4<<2));
      *(float4*)(Whs + r*320 + gg*20 + (k4<<2)) = v;
    }
    if(tid < 32) mskbits[tid] = mrow[tid*(N_/32) + (j0>>5)];
    if(tid < H*32){
      int hh = tid>>5, jj = tid&31;
      s2s[hh][jj] = s2p[hh*N_ + j0 + jj];
    }
    __syncthreads();

    unsigned mb0 = mskbits[is], mb1 = mskbits[is+16];

    #pragma unroll 4
    for(int jj=0;jj<32;jj++){
      float s2v = s2s[h][jj];
      float e0 = s1v0 + s2v; e0 = fmaxf(e0, 0.2f*e0); e0 = ((mb0>>jj)&1u) ? e0 : NEGC;
      float e1 = s1v1 + s2v; e1 = fmaxf(e1, 0.2f*e1); e1 = ((mb1>>jj)&1u) ? e1 : NEGC;
      float p0 = ex2f(fmaf(e0, LOG2E, nm0)); l0 += p0;
      float p1 = ex2f(fmaf(e1, LOG2E, nm1)); l1 += p1;
      unsigned long long P0 = bcast2(p0), P1 = bcast2(p1);
      const ulonglong2* wp = (const ulonglong2*)(Whs + jj*320 + g*20);
      ulonglong2 wa = wp[0], wb = wp[1], wc = wp[2], wd = wp[3];
      FMA2(acc0p[0],P0,wa.x); FMA2(acc0p[1],P0,wa.y);
      FMA2(acc0p[2],P0,wb.x); FMA2(acc0p[3],P0,wb.y);
      FMA2(acc0p[4],P0,wc.x); FMA2(acc0p[5],P0,wc.y);
      FMA2(acc0p[6],P0,wd.x); FMA2(acc0p[7],P0,wd.y);
      FMA2(acc1p[0],P1,wa.x); FMA2(acc1p[1],P1,wa.y);
      FMA2(acc1p[2],P1,wb.x); FMA2(acc1p[3],P1,wb.y);
      FMA2(acc1p[4],P1,wc.x); FMA2(acc1p[5],P1,wc.y);
      FMA2(acc1p[6],P1,wd.x); FMA2(acc1p[7],P1,wd.y);
    }
  }

  float inv0 = (l0>0.f) ? 1.f/l0 : 0.f;
  float inv1 = (l1>0.f) ? 1.f/l1 : 0.f;
  float v0[16], v1[16];
  #pragma unroll
  for(int k=0;k<8;k++){
    float2 a = unpack2(acc0p[k]); v0[2*k] = a.x; v0[2*k+1] = a.y;
    float2 c = unpack2(acc1p[k]); v1[2*k] = c.x; v1[2*k+1] = c.y;
  }
  float* p0o = out + ((b*N_ + q0)<<8) + c0;
  float* p1o = out + ((b*N_ + q1)<<8) + c0;
  #pragma unroll
  for(int k4=0;k4<4;k4++){
    float4 o0, o1; float t;
    t = v0[k4*4+0]*inv0; t=eluf(t); if(elu2) t=eluf(t); o0.x=t;
    t = v0[k4*4+1]*inv0; t=eluf(t); if(elu2) t=eluf(t); o0.y=t;
    t = v0[k4*4+2]*inv0; t=eluf(t); if(elu2) t=eluf(t); o0.z=t;
    t = v0[k4*4+3]*inv0; t=eluf(t); if(elu2) t=eluf(t); o0.w=t;
    t = v1[k4*4+0]*inv1; t=eluf(t); if(elu2) t=eluf(t); o1.x=t;
    t = v1[k4*4+1]*inv1; t=eluf(t); if(elu2) t=eluf(t); o1.y=t;
    t = v1[k4*4+2]*inv1; t=eluf(t); if(elu2) t=eluf(t); o1.z=t;
    t = v1[k4*4+3]*inv1; t=eluf(t); if(elu2) t=eluf(t); o1.w=t;
    *(float4*)(p0o + (k4<<2)) = o0;
    *(float4*)(p1o + (k4<<2)) = o1;
  }
}

extern "C" void kernel_launch(void* const* d_in, const int* in_sizes, int n_in,
                              void* d_out, int out_size){
  const float* x       = (const float*)d_in[0];
  const int*   adj     = (const int*)  d_in[1];
  const float* W_heads = (const float*)d_in[2];  // [3,8,256,32]
  const float* a_heads = (const float*)d_in[3];  // [3,8,64]
  const float* W_out   = (const float*)d_in[4];  // [3,256,256]
  const float* a_out   = (const float*)d_in[5];  // [3,512]
  float* outp = (float*)d_out;

  maskpack_kernel<<<(B_*N_)/8,256>>>(adj);

  for(int l=0;l<3;l++){
    // ---- multi-head pass ----
    pack_w_kernel<<<256,256>>>(W_heads + l*8*F_*32);
    gemm_kernel<<<dim3(4,64),256>>>(x, (l==0)?0:1, (const float*)nullptr, 1);
    scores_kernel<<<(B_*8*N_)/8,256>>>(a_heads + l*8*64, 8, 32);
    s2max_kernel<<<B_*8,256>>>(8);
    attn_kernel<<<128,256>>>((float*)nullptr, 2, 8, 32, 0);
    // ---- single-head output pass ----
    gemm_kernel<<<dim3(4,64),256>>>((const float*)nullptr, 2, W_out + l*F_*F_, 0);
    scores_kernel<<<(B_*N_)/8,256>>>(a_out + l*2*F_, 1, 256);
    s2max_kernel<<<B_,256>>>(1);
    attn_kernel<<<128,256>>>(outp, (l==2)?0:1, 1, 256, 1);
  }
}

// round 8
// speedup vs baseline: 1.6472x; 1.3640x over previous
#include <cuda_runtime.h>
#include <math.h>

#define B_ 2
#define N_ 2048
#define F_ 256
#define NEGC (-1e15f)
#define LOG2E 1.4426950408889634f
#define JS 8                 // j-splits per attention pass
#define JPU (N_/JS)          // 256 j per work unit

// ---------------- scratch (no allocations allowed) ----------------
__device__ float    g_bufA[B_*N_*F_];
__device__ float    g_bufB[B_*N_*F_];
__device__ float    g_Wh  [B_*N_*F_];
__device__ float    g_Wcat[F_*F_];
__device__ float    g_s1  [B_*8*N_];
__device__ float    g_s2  [B_*8*N_];
__device__ float    g_mx2 [B_*8];          // global max of s2 per (b,h)
__device__ unsigned g_msk [B_*N_*(N_/32)]; // packed adjacency bits
__device__ float    g_pacc[JS][B_*N_*F_];  // partial P·V per j-split
__device__ float    g_pl  [JS][B_*8*N_];   // partial softmax denom per j-split

__device__ __forceinline__ float eluf(float x){ return x > 0.f ? x : expm1f(x); }
__device__ __forceinline__ float ex2f(float x){ float r; asm("ex2.approx.f32 %0, %1;":"=f"(r):"f"(x)); return r; }

// packed f32x2 helpers (FFMA2 path: only reachable via PTX fma.rn.f32x2)
#define FMA2(acc, p, w) asm("fma.rn.f32x2 %0, %1, %2, %0;" : "+l"(acc) : "l"(p), "l"(w))
__device__ __forceinline__ unsigned long long bcast2(float x){
  unsigned long long r; unsigned xi = __float_as_uint(x);
  asm("mov.b64 %0, {%1, %1};" : "=l"(r) : "r"(xi));
  return r;
}
__device__ __forceinline__ float2 unpack2(unsigned long long v){
  unsigned lo, hi;
  asm("mov.b64 {%0, %1}, %2;" : "=r"(lo), "=r"(hi) : "l"(v));
  return make_float2(__uint_as_float(lo), __uint_as_float(hi));
}

// pack adjacency into bitmask words, once per launch. warp per row.
__global__ void maskpack_kernel(const int* __restrict__ adj){
  int row  = blockIdx.x*8 + (threadIdx.x>>5);   // 0..B*N-1, grid=512
  int lane = threadIdx.x & 31;
  const int* ar = adj + (long)row*N_;
  unsigned* mw = g_msk + row*(N_/32);
  for(int w=0; w<N_/32; w++){
    int a = ar[w*32 + lane];
    unsigned bal = __ballot_sync(0xffffffffu, a != 0);
    if(lane==0) mw[w] = bal;
  }
}

// pack W_heads[l] (H=8, F, O=32) -> g_Wcat[F][F] with Wcat[f][h*32+o] = W[h][f][o]
__global__ void pack_w_kernel(const float* __restrict__ Wsrc){
  int idx = blockIdx.x*256 + threadIdx.x;   // 0..65535
  int col = idx & 255, f = idx >> 8;
  int h = col >> 5, o = col & 31;
  g_Wcat[idx] = Wsrc[(h*F_ + f)*32 + o];
}

// C[M,256] = A[M,256] @ W[256,256] ; M = B_*N_ = 4096 ; C = g_Wh. FFMA2 inner.
__global__ __launch_bounds__(256) void gemm_kernel(const float* __restrict__ Aext, int asel,
                                                   const float* __restrict__ Wext, int wsel){
  const float* A = (asel==0) ? Aext : (asel==1 ? g_bufA : g_bufB);
  const float* W = (wsel==0) ? Wext : g_Wcat;
  float* C = g_Wh;
  __shared__ __align__(16) float As[16][68];
  __shared__ __align__(16) float Bs[16][68];
  int bm = blockIdx.y*64, bn = blockIdx.x*64;
  int tid = threadIdx.x;
  int tm = (tid>>4)<<2, tn = (tid&15)<<2;
  unsigned long long accp[4][2];
  #pragma unroll
  for(int i=0;i<4;i++){ accp[i][0]=0ull; accp[i][1]=0ull; }
  for(int k0=0;k0<256;k0+=16){
    __syncthreads();
    #pragma unroll
    for(int t=0;t<4;t++){
      int u = tid + t*256;               // 0..1023
      int r = u>>4, c = u&15;
      As[c][r]   = A[(bm+r)*256 + k0 + c];
      int r2 = u>>6, c2 = u&63;
      Bs[r2][c2] = W[(k0+r2)*256 + bn + c2];
    }
    __syncthreads();
    #pragma unroll
    for(int kk=0;kk<16;kk++){
      float4 a4 = *(const float4*)&As[kk][tm];
      ulonglong2 b2 = *(const ulonglong2*)&Bs[kk][tn];
      unsigned long long P;
      P = bcast2(a4.x); FMA2(accp[0][0],P,b2.x); FMA2(accp[0][1],P,b2.y);
      P = bcast2(a4.y); FMA2(accp[1][0],P,b2.x); FMA2(accp[1][1],P,b2.y);
      P = bcast2(a4.z); FMA2(accp[2][0],P,b2.x); FMA2(accp[2][1],P,b2.y);
      P = bcast2(a4.w); FMA2(accp[3][0],P,b2.x); FMA2(accp[3][1],P,b2.y);
    }
  }
  #pragma unroll
  for(int i=0;i<4;i++){
    float2 lo = unpack2(accp[i][0]), hi = unpack2(accp[i][1]);
    *(float4*)&C[(bm+tm+i)*256 + bn + tn] = make_float4(lo.x,lo.y,hi.x,hi.y);
  }
}

// s1[b,h,n] = Wh[b,n,h*O:..]·a1h ; s2 likewise. One warp per row; rows = B*H*N.
__global__ void scores_kernel(const float* __restrict__ avec, int H, int O){
  int lane = threadIdx.x & 31;
  int wid  = threadIdx.x >> 5;
  int row  = blockIdx.x*8 + wid;          // grid sized exactly
  int n = row % N_;
  int h = (row / N_) % H;
  int b = row / (N_*H);
  const float* w = g_Wh + (b*N_ + n)*F_ + h*O;
  const float* a = avec + h*2*O;
  float r1=0.f, r2=0.f;
  for(int o=lane;o<O;o+=32){
    float v = w[o];
    r1 += v*a[o];
    r2 += v*a[O+o];
  }
  #pragma unroll
  for(int d=16;d;d>>=1){
    r1 += __shfl_xor_sync(0xffffffffu, r1, d);
    r2 += __shfl_xor_sync(0xffffffffu, r2, d);
  }
  if(lane==0){ g_s1[row]=r1; g_s2[row]=r2; }
}

// Global (unmasked) max of s2 per (b,h): valid softmax upper bound via lrelu
// monotonicity; makes partial sums over j-splits directly addable. grid = B*H.
__global__ void s2max_kernel(int H){
  int bh = blockIdx.x;
  const float* p = g_s2 + bh*N_;
  float v = -INFINITY;
  for(int j=threadIdx.x;j<N_;j+=256) v = fmaxf(v, p[j]);
  __shared__ float red[8];
  int lane = threadIdx.x & 31, wid = threadIdx.x >> 5;
  #pragma unroll
  for(int d=16;d;d>>=1) v = fmaxf(v, __shfl_xor_sync(0xffffffffu, v, d));
  if(lane==0) red[wid] = v;
  __syncthreads();
  if(wid==0){
    v = red[lane&7];
    #pragma unroll
    for(int d=4;d;d>>=1) v = fmaxf(v, __shfl_xor_sync(0xffffffffu, v, d));
    if(lane==0) g_mx2[bh] = v;
  }
}

// Partial-sum attention: unit = (b, 32-query block, j-split). Fixed global m
// -> partials (sum p*Wh, sum p) add exactly; combine kernel finishes.
// 256 thr: warp w covers col-groups (w&1)*8..+8 and query-slots (w>>1)*4..+4;
// per LDS.128 a warp touches 8 bank-distinct lines (stride-20), 4-lane bcast.
// H==1: p(q,j) shared across all 16 col-groups via a per-chunk SMEM p-tile.
template<int H>
__global__ __launch_bounds__(256,2) void attn_part_kernel(){
  int unit = blockIdx.x;               // 0..1023
  int ib = unit & 127;
  int jy = unit >> 7;
  int b  = ib >> 6;
  int i0 = (ib & 63) << 5;
  int tid = threadIdx.x;
  int w  = tid >> 5, lane = tid & 31;
  int g  = (w&1)*8 + (lane>>2);        // 16 col groups of 16
  int is = (w>>1)*4 + (lane&3);        // 16 query slots
  int c0 = g << 4;
  int h  = (H==8) ? (g>>1) : 0;
  int q0 = i0 + is, q1 = q0 + 16;

  __shared__ __align__(16) float Whs[32*320];  // 16 groups, stride 20 floats
  __shared__ float s2s[8][33];                 // H=8 path
  __shared__ unsigned mskbits[32];             // H=8 path
  __shared__ __align__(16) float2 ps2[512];    // H=1 path: p-tile (jj*16+is)

  const float* Wh = g_Wh;
  unsigned long long acc0p[8], acc1p[8];
  #pragma unroll
  for(int k=0;k<8;k++){ acc0p[k]=0ull; acc1p[k]=0ull; }
  float l0=0.f, l1=0.f;

  float mxv = g_mx2[b*H + h];
  const float* s1p = g_s1 + (b*H + h)*N_;
  float s1v0 = s1p[q0], s1v1 = s1p[q1];
  float u0 = s1v0 + mxv; u0 = fmaxf(u0, 0.2f*u0);
  float u1 = s1v1 + mxv; u1 = fmaxf(u1, 0.2f*u1);
  float nm0 = -u0*LOG2E, nm1 = -u1*LOG2E;   // exp(e-m) = ex2(e*log2e + nm)
  const float* s2p = g_s2 + b*H*N_;
  const unsigned* mrow = g_msk + (b*N_ + i0)*(N_/32);

  // hoisted state for H==1 p-tile producer role
  int isP=0, jjP=0;
  float s1A=0,s1B=0,s1C=0,s1D=0, nmA=0,nmB=0,nmC=0,nmD=0;
  if constexpr (H==1){
    isP = (2*tid) & 15;                // even
    jjP = tid >> 3;                    // 0..31
    const float* s1b = g_s1 + b*N_;
    s1A = s1b[i0+isP];    s1B = s1b[i0+isP+1];
    s1C = s1b[i0+16+isP]; s1D = s1b[i0+17+isP];
    float t;
    t = s1A+mxv; t = fmaxf(t,0.2f*t); nmA = -t*LOG2E;
    t = s1B+mxv; t = fmaxf(t,0.2f*t); nmB = -t*LOG2E;
    t = s1C+mxv; t = fmaxf(t,0.2f*t); nmC = -t*LOG2E;
    t = s1D+mxv; t = fmaxf(t,0.2f*t); nmD = -t*LOG2E;
  }

  int jbase = jy*JPU;
  for(int jc=0;jc<JPU/32;jc++){
    int j0 = jbase + jc*32;
    __syncthreads();
    // load 32x256 Wh j-tile into group-padded layout
    #pragma unroll
    for(int t=0;t<8;t++){
      int u = tid + t*256;               // 0..2047 float4 units
      int r = u>>6, c4 = u&63;
      int gg = c4>>2, k4 = c4&3;
      float4 v = *(const float4*)(Wh + ((b*N_ + j0 + r)<<8) + (c4<<2));
      *(float4*)(Whs + r*320 + gg*20 + (k4<<2)) = v;
    }
    if constexpr (H==8){
      if(tid < 32) mskbits[tid] = mrow[tid*(N_/32) + (j0>>5)];
      {
        int hh = tid>>5, jj = tid&31;
        s2s[hh][jj] = s2p[hh*N_ + j0 + jj];
      }
    } else {
      // p-tile producer: each thread computes 4 p values (2 is x 2 q-halves)
      float s2v = g_s2[b*N_ + j0 + jjP];
      int widx = j0 >> 5;
      const unsigned* mb = g_msk + (b*N_ + i0)*(N_/32) + widx;
      unsigned mA = mb[isP*64],      mB = mb[(isP+1)*64];
      unsigned mC = mb[(isP+16)*64], mD = mb[(isP+17)*64];
      float t, pA, pB, pC, pD;
      t = s1A + s2v; t = fmaxf(t, 0.2f*t);
      pA = ((mA>>jjP)&1u) ? ex2f(fmaf(t, LOG2E, nmA)) : 0.f;
      t = s1B + s2v; t = fmaxf(t, 0.2f*t);
      pB = ((mB>>jjP)&1u) ? ex2f(fmaf(t, LOG2E, nmB)) : 0.f;
      t = s1C + s2v; t = fmaxf(t, 0.2f*t);
      pC = ((mC>>jjP)&1u) ? ex2f(fmaf(t, LOG2E, nmC)) : 0.f;
      t = s1D + s2v; t = fmaxf(t, 0.2f*t);
      pD = ((mD>>jjP)&1u) ? ex2f(fmaf(t, LOG2E, nmD)) : 0.f;
      *(float4*)&ps2[jjP*16 + isP] = make_float4(pA, pC, pB, pD);
    }
    __syncthreads();

    unsigned mb0=0, mb1=0;
    if constexpr (H==8){ mb0 = mskbits[is]; mb1 = mskbits[is+16]; }

    #pragma unroll 4
    for(int jj=0;jj<32;jj++){
      float p0, p1;
      if constexpr (H==8){
        float s2v = s2s[h][jj];
        float e0 = s1v0 + s2v; e0 = fmaxf(e0, 0.2f*e0); e0 = ((mb0>>jj)&1u) ? e0 : NEGC;
        float e1 = s1v1 + s2v; e1 = fmaxf(e1, 0.2f*e1); e1 = ((mb1>>jj)&1u) ? e1 : NEGC;
        p0 = ex2f(fmaf(e0, LOG2E, nm0));
        p1 = ex2f(fmaf(e1, LOG2E, nm1));
      } else {
        float2 pv = ps2[jj*16 + is];
        p0 = pv.x; p1 = pv.y;
      }
      l0 += p0; l1 += p1;
      unsigned long long P0 = bcast2(p0), P1 = bcast2(p1);
      const ulonglong2* wp = (const ulonglong2*)(Whs + jj*320 + g*20);
      ulonglong2 wa = wp[0], wb = wp[1], wc = wp[2], wd = wp[3];
      FMA2(acc0p[0],P0,wa.x); FMA2(acc0p[1],P0,wa.y);
      FMA2(acc0p[2],P0,wb.x); FMA2(acc0p[3],P0,wb.y);
      FMA2(acc0p[4],P0,wc.x); FMA2(acc0p[5],P0,wc.y);
      FMA2(acc0p[6],P0,wd.x); FMA2(acc0p[7],P0,wd.y);
      FMA2(acc1p[0],P1,wa.x); FMA2(acc1p[1],P1,wa.y);
      FMA2(acc1p[2],P1,wb.x); FMA2(acc1p[3],P1,wb.y);
      FMA2(acc1p[4],P1,wc.x); FMA2(acc1p[5],P1,wc.y);
      FMA2(acc1p[6],P1,wd.x); FMA2(acc1p[7],P1,wd.y);
    }
  }

  // write raw partials (no divide/elu here)
  float* pacc = g_pacc[jy];
  float* p0o = pacc + ((b*N_ + q0)<<8) + c0;
  float* p1o = pacc + ((b*N_ + q1)<<8) + c0;
  #pragma unroll
  for(int k=0;k<4;k++){
    float2 a = unpack2(acc0p[2*k]),   bb = unpack2(acc0p[2*k+1]);
    float2 c = unpack2(acc1p[2*k]),   d  = unpack2(acc1p[2*k+1]);
    *(float4*)(p0o + (k<<2)) = make_float4(a.x,a.y,bb.x,bb.y);
    *(float4*)(p1o + (k<<2)) = make_float4(c.x,c.y,d.x,d.y);
  }
  bool lw = (H==8) ? ((g&1)==0) : (g==0);
  if(lw){
    g_pl[jy][(b*H+h)*N_ + q0] = l0;
    g_pl[jy][(b*H+h)*N_ + q1] = l1;
  }
}

// combine: out = elu^(1 or 2)( (sum_s acc_s) / (sum_s l_s) ). block = one row.
__global__ __launch_bounds__(256) void combine_kernel(float* __restrict__ out_ext,
        int osel, int H, int elu2){
  float* out = (osel==0) ? out_ext : (osel==1 ? g_bufA : g_bufB);
  int row = blockIdx.x;                // b*N+q, 0..4095
  int c = threadIdx.x;
  int b = row >> 11, q = row & (N_-1);
  int h = (H==8) ? (c>>5) : 0;
  float acc = 0.f, l = 0.f;
  #pragma unroll
  for(int s=0;s<JS;s++) acc += g_pacc[s][(row<<8) + c];
  #pragma unroll
  for(int s=0;s<JS;s++) l += g_pl[s][(b*H+h)*N_ + q];
  float inv = (l>0.f) ? 1.f/l : 0.f;
  float t = acc*inv; t = eluf(t); if(elu2) t = eluf(t);
  out[(row<<8) + c] = t;
}

extern "C" void kernel_launch(void* const* d_in, const int* in_sizes, int n_in,
                              void* d_out, int out_size){
  const float* x       = (const float*)d_in[0];
  const int*   adj     = (const int*)  d_in[1];
  const float* W_heads = (const float*)d_in[2];  // [3,8,256,32]
  const float* a_heads = (const float*)d_in[3];  // [3,8,64]
  const float* W_out   = (const float*)d_in[4];  // [3,256,256]
  const float* a_out   = (const float*)d_in[5];  // [3,512]
  float* outp = (float*)d_out;

  maskpack_kernel<<<(B_*N_)/8,256>>>(adj);

  for(int l=0;l<3;l++){
    // ---- multi-head pass ----
    pack_w_kernel<<<256,256>>>(W_heads + l*8*F_*32);
    gemm_kernel<<<dim3(4,64),256>>>(x, (l==0)?0:1, (const float*)nullptr, 1);
    scores_kernel<<<(B_*8*N_)/8,256>>>(a_heads + l*8*64, 8, 32);
    s2max_kernel<<<B_*8,256>>>(8);
    attn_part_kernel<8><<<128*JS,256>>>();
    combine_kernel<<<B_*N_,256>>>((float*)nullptr, 2, 8, 0);
    // ---- single-head output pass ----
    gemm_kernel<<<dim3(4,64),256>>>((const float*)nullptr, 2, W_out + l*F_*F_, 0);
    scores_kernel<<<(B_*N_)/8,256>>>(a_out + l*2*F_, 1, 256);
    s2max_kernel<<<B_,256>>>(1);
    attn_part_kernel<1><<<128*JS,256>>>();
    combine_kernel<<<B_*N_,256>>>(outp, (l==2)?0:1, 1, 1);
  }
}